// round 3
// baseline (speedup 1.0000x reference)
#include <cuda_runtime.h>
#include <cuda_bf16.h>
#include <mma.h>
#include <cstdint>

using namespace nvcuda;

// Problem dims
#define BB   2
#define SS   2048
#define DIM  2048
#define HH   16
#define HD   128

// ---------------------------------------------------------------------------
// Scratch: Q,K,V in [B,H,S,HD] fp32 layout. One device-global scratch blob,
// partitioned by constant offsets (33.5 MB each).
// ---------------------------------------------------------------------------
#define QKV_ELEMS (BB * HH * SS * HD)
__device__ float g_scratch[3 * QKV_ELEMS];

__device__ __forceinline__ float f2tf32(float x) {
    // round-to-nearest tf32 (truncation would bias ~1e-3)
    uint32_t u;
    asm("cvt.rna.tf32.f32 %0, %1;" : "=r"(u) : "f"(x));
    return __uint_as_float(u);
}

// ---------------------------------------------------------------------------
// Fused projection GEMM: for z in {0,1,2}:
//   C_z[4096,2048] = A[4096,2048] @ W_z[2048,2048]
// Block tile 128x128, K-tile 32, double-buffered smem, wmma tf32 16x16x8.
// Output written directly into [B,H,S,HD] layout (N-tile == one head).
// grid = (16, 32, 3): z selects {Wq->Q, Wk->K, Wv->V}.
// ---------------------------------------------------------------------------
#define GEMM_SMEM_FLOATS (2 * (128 * 36) + 2 * (32 * 132))
#define GEMM_SMEM_BYTES  (GEMM_SMEM_FLOATS * 4)

__global__ void __launch_bounds__(256, 1)
proj_gemm_fused(const float* __restrict__ A,
                const float* __restrict__ Wq,
                const float* __restrict__ Wk,
                const float* __restrict__ Wv,
                float* __restrict__ scratch) {
    extern __shared__ float sm[];
    float* As[2] = { sm, sm + 128 * 36 };
    float* Bs[2] = { sm + 2 * 128 * 36, sm + 2 * 128 * 36 + 32 * 132 };

    const int tid  = threadIdx.x;
    const int warp = tid >> 5;
    const int wm   = warp >> 2;   // 0..1
    const int wn   = warp & 3;    // 0..3
    const int bm   = blockIdx.y;  // 0..31
    const int bn   = blockIdx.x;  // 0..15
    const int z    = blockIdx.z;  // 0..2

    const float* Wm = (z == 0) ? Wq : (z == 1) ? Wk : Wv;
    float* outp = scratch + (size_t)z * QKV_ELEMS;

    const float* Ag = A + (size_t)bm * 128 * DIM;
    const float* Bg = Wm + bn * 128;

    wmma::fragment<wmma::accumulator, 16, 16, 8, float> acc[4][2];
#pragma unroll
    for (int i = 0; i < 4; ++i)
#pragma unroll
        for (int j = 0; j < 2; ++j) wmma::fill_fragment(acc[i][j], 0.0f);

    // per-thread load slots
    const int ar = tid >> 3;          // 0..31 (row stride 32 per pass)
    const int ac = (tid & 7) * 4;     // col within 32
    const int bk = tid >> 5;          // 0..7  (k stride 8 per pass)
    const int bc = (tid & 31) * 4;    // col within 128

    float4 ra[4], rb[4];

    // prologue load kt=0
#pragma unroll
    for (int p = 0; p < 4; ++p)
        ra[p] = *(const float4*)(Ag + (size_t)(p * 32 + ar) * DIM + ac);
#pragma unroll
    for (int p = 0; p < 4; ++p)
        rb[p] = *(const float4*)(Bg + (size_t)(p * 8 + bk) * DIM + bc);
#pragma unroll
    for (int p = 0; p < 4; ++p) {
        float* d = As[0] + (p * 32 + ar) * 36 + ac;
        d[0] = f2tf32(ra[p].x); d[1] = f2tf32(ra[p].y);
        d[2] = f2tf32(ra[p].z); d[3] = f2tf32(ra[p].w);
    }
#pragma unroll
    for (int p = 0; p < 4; ++p) {
        float* d = Bs[0] + (p * 8 + bk) * 132 + bc;
        d[0] = f2tf32(rb[p].x); d[1] = f2tf32(rb[p].y);
        d[2] = f2tf32(rb[p].z); d[3] = f2tf32(rb[p].w);
    }
    __syncthreads();

    const int NKT = DIM / 32;  // 64
#pragma unroll 1
    for (int kt = 0; kt < NKT; ++kt) {
        const int buf = kt & 1;
        if (kt < NKT - 1) {
            const int ko = (kt + 1) * 32;
#pragma unroll
            for (int p = 0; p < 4; ++p)
                ra[p] = *(const float4*)(Ag + (size_t)(p * 32 + ar) * DIM + ko + ac);
#pragma unroll
            for (int p = 0; p < 4; ++p)
                rb[p] = *(const float4*)(Bg + (size_t)(ko + p * 8 + bk) * DIM + bc);
        }
        // compute on buf
#pragma unroll
        for (int ks = 0; ks < 4; ++ks) {
            wmma::fragment<wmma::matrix_a, 16, 16, 8, wmma::precision::tf32, wmma::row_major> fa[4];
            wmma::fragment<wmma::matrix_b, 16, 16, 8, wmma::precision::tf32, wmma::row_major> fb[2];
#pragma unroll
            for (int i = 0; i < 4; ++i)
                wmma::load_matrix_sync(fa[i], As[buf] + (wm * 64 + i * 16) * 36 + ks * 8, 36);
#pragma unroll
            for (int j = 0; j < 2; ++j)
                wmma::load_matrix_sync(fb[j], Bs[buf] + (ks * 8) * 132 + wn * 32 + j * 16, 132);
#pragma unroll
            for (int i = 0; i < 4; ++i)
#pragma unroll
                for (int j = 0; j < 2; ++j)
                    wmma::mma_sync(acc[i][j], fa[i], fb[j], acc[i][j]);
        }
        if (kt < NKT - 1) {
            const int nb = buf ^ 1;
#pragma unroll
            for (int p = 0; p < 4; ++p) {
                float* d = As[nb] + (p * 32 + ar) * 36 + ac;
                d[0] = f2tf32(ra[p].x); d[1] = f2tf32(ra[p].y);
                d[2] = f2tf32(ra[p].z); d[3] = f2tf32(ra[p].w);
            }
#pragma unroll
            for (int p = 0; p < 4; ++p) {
                float* d = Bs[nb] + (p * 8 + bk) * 132 + bc;
                d[0] = f2tf32(rb[p].x); d[1] = f2tf32(rb[p].y);
                d[2] = f2tf32(rb[p].z); d[3] = f2tf32(rb[p].w);
            }
        }
        __syncthreads();
    }

    // epilogue: map (m = bm*128 + r, n = bn*128 + c) -> [b, h, s, d]
    // b = bm/16, s0 = (bm%16)*128, h = bn (N-tile of 128 == one head)
    const int b  = bm >> 4;
    const int s0 = (bm & 15) * 128;
    float* Cg = outp + (((size_t)(b * HH + bn)) * SS + s0) * HD;
#pragma unroll
    for (int i = 0; i < 4; ++i)
#pragma unroll
        for (int j = 0; j < 2; ++j)
            wmma::store_matrix_sync(Cg + (wm * 64 + i * 16) * HD + wn * 32 + j * 16,
                                    acc[i][j], HD, wmma::mem_row_major);
}

// ---------------------------------------------------------------------------
// Flash attention, causal, fp32 with tf32 tensor ops.
// CTA: 64 Q-rows, 8 warps. KV loop truncated by causality.
// Heavy blocks (large qb) scheduled first: qb = 31 - blockIdx.x.
// smem: Qs/Ks/Vs/Os [64][132], Ps [64][68], mrow/lrow [64]
// ---------------------------------------------------------------------------
#define ATT_SMEM_FLOATS (4 * 64 * 132 + 64 * 68 + 128)
#define ATT_SMEM_BYTES  (ATT_SMEM_FLOATS * 4)

__global__ void __launch_bounds__(256, 1)
attn_kernel(const float* __restrict__ Q, const float* __restrict__ K,
            const float* __restrict__ V, float* __restrict__ outp) {
    extern __shared__ float sm[];
    float* Qs   = sm;                 // 64 x 132
    float* Ks   = Qs + 64 * 132;
    float* Vs   = Ks + 64 * 132;
    float* Os   = Vs + 64 * 132;
    float* Ps   = Os + 64 * 132;      // 64 x 68
    float* mrow = Ps + 64 * 68;       // 64
    float* lrow = mrow + 64;          // 64

    const int qb  = (gridDim.x - 1) - blockIdx.x;  // heavy blocks first
    const int bh  = blockIdx.y;       // 0..31
    const int tid = threadIdx.x;
    const int warp = tid >> 5;

    const float scale = 0.08838834764831845f;  // 1/sqrt(128)
    const float* Qg = Q + ((size_t)bh * SS + qb * 64) * HD;

    for (int idx = tid; idx < 64 * 128; idx += 256) {
        const int r = idx >> 7, d = idx & 127;
        Qs[r * 132 + d] = f2tf32(Qg[r * 128 + d] * scale);
        Os[r * 132 + d] = 0.0f;
    }
    if (tid < 64) { mrow[tid] = -1e30f; lrow[tid] = 0.0f; }
    __syncthreads();

#pragma unroll 1
    for (int kb = 0; kb <= qb; ++kb) {
        const float* Kg = K + ((size_t)bh * SS + kb * 64) * HD;
        const float* Vg = V + ((size_t)bh * SS + kb * 64) * HD;
        for (int idx = tid; idx < 64 * 128; idx += 256) {
            const int r = idx >> 7, d = idx & 127;
            Ks[r * 132 + d] = f2tf32(Kg[r * 128 + d]);
            Vs[r * 132 + d] = f2tf32(Vg[r * 128 + d]);
        }
        __syncthreads();

        // S = Qs @ Ks^T (64x64); 16 tiles of 16x16, 2 per warp
#pragma unroll
        for (int i = 0; i < 2; ++i) {
            const int ti = warp * 2 + i;
            const int tm = ti >> 2, tn = ti & 3;
            wmma::fragment<wmma::accumulator, 16, 16, 8, float> acc;
            wmma::fill_fragment(acc, 0.0f);
#pragma unroll
            for (int k = 0; k < 128; k += 8) {
                wmma::fragment<wmma::matrix_a, 16, 16, 8, wmma::precision::tf32, wmma::row_major> fa;
                wmma::fragment<wmma::matrix_b, 16, 16, 8, wmma::precision::tf32, wmma::col_major> fb;
                wmma::load_matrix_sync(fa, Qs + (tm * 16) * 132 + k, 132);
                wmma::load_matrix_sync(fb, Ks + (tn * 16) * 132 + k, 132);
                wmma::mma_sync(acc, fa, fb, acc);
            }
            wmma::store_matrix_sync(Ps + (tm * 16) * 68 + tn * 16, acc, 68, wmma::mem_row_major);
        }
        __syncthreads();

        // online softmax: row r handled by 4 consecutive lanes
        {
            const int r = tid >> 2, g = tid & 3;
            const bool diag = (kb == qb);
            float vals[16];
            float mloc = -1e30f;
#pragma unroll
            for (int j = 0; j < 16; ++j) {
                const int c = g + j * 4;
                float v = Ps[r * 68 + c];
                if (diag && c > r) v = -1e30f;
                vals[j] = v;
                mloc = fmaxf(mloc, v);
            }
            mloc = fmaxf(mloc, __shfl_xor_sync(0xffffffffu, mloc, 1));
            mloc = fmaxf(mloc, __shfl_xor_sync(0xffffffffu, mloc, 2));
            const float mold = mrow[r];
            const float mnew = fmaxf(mold, mloc);
            const float alpha = __expf(mold - mnew);
            float ssum = 0.0f;
#pragma unroll
            for (int j = 0; j < 16; ++j) {
                const float p = __expf(vals[j] - mnew);
                ssum += p;
                Ps[r * 68 + g + j * 4] = f2tf32(p);
            }
            ssum += __shfl_xor_sync(0xffffffffu, ssum, 1);
            ssum += __shfl_xor_sync(0xffffffffu, ssum, 2);
            if (g == 0) { lrow[r] = lrow[r] * alpha + ssum; mrow[r] = mnew; }
            // rescale O row by alpha (4 lanes x 32 cols)
#pragma unroll
            for (int j = 0; j < 32; ++j) Os[r * 132 + g * 32 + j] *= alpha;
        }
        __syncthreads();

        // O += P @ V ; warp w owns column tile w (16 cols), all 4 row tiles
#pragma unroll
        for (int tm = 0; tm < 4; ++tm) {
            wmma::fragment<wmma::accumulator, 16, 16, 8, float> acc;
            wmma::load_matrix_sync(acc, Os + (tm * 16) * 132 + warp * 16, 132, wmma::mem_row_major);
#pragma unroll
            for (int k = 0; k < 64; k += 8) {
                wmma::fragment<wmma::matrix_a, 16, 16, 8, wmma::precision::tf32, wmma::row_major> fa;
                wmma::fragment<wmma::matrix_b, 16, 16, 8, wmma::precision::tf32, wmma::row_major> fb;
                wmma::load_matrix_sync(fa, Ps + (tm * 16) * 68 + k, 68);
                wmma::load_matrix_sync(fb, Vs + k * 132 + warp * 16, 132);
                wmma::mma_sync(acc, fa, fb, acc);
            }
            wmma::store_matrix_sync(Os + (tm * 16) * 132 + warp * 16, acc, 132, wmma::mem_row_major);
        }
        __syncthreads();
    }

    // epilogue: O / l
    float* Og = outp + ((size_t)bh * SS + qb * 64) * HD;
    for (int idx = tid; idx < 64 * 128; idx += 256) {
        const int r = idx >> 7, d = idx & 127;
        Og[r * 128 + d] = Os[r * 132 + d] / lrow[r];
    }
}

// ---------------------------------------------------------------------------
// kernel_launch
// inputs: [0]=hidden_states fp32 [2,2048,2048], [1]=attention_mask (causal,
//         reconstructed analytically, unused), [2]=Wq, [3]=Wk, [4]=Wv
// output: fp32 [2,16,2048,128]
// ---------------------------------------------------------------------------
extern "C" void kernel_launch(void* const* d_in, const int* in_sizes, int n_in,
                              void* d_out, int out_size) {
    const float* hs = (const float*)d_in[0];
    const float* Wq = (const float*)d_in[2];
    const float* Wk = (const float*)d_in[3];
    const float* Wv = (const float*)d_in[4];
    float* out = (float*)d_out;

    float* base = nullptr;
    cudaGetSymbolAddress((void**)&base, g_scratch);
    float* qp = base;
    float* kp = base + QKV_ELEMS;
    float* vp = base + 2 * QKV_ELEMS;

    cudaFuncSetAttribute(proj_gemm_fused, cudaFuncAttributeMaxDynamicSharedMemorySize, GEMM_SMEM_BYTES);
    cudaFuncSetAttribute(attn_kernel, cudaFuncAttributeMaxDynamicSharedMemorySize, ATT_SMEM_BYTES);

    dim3 ggrid(DIM / 128, (BB * SS) / 128, 3);  // 16 x 32 x 3
    proj_gemm_fused<<<ggrid, 256, GEMM_SMEM_BYTES>>>(hs, Wq, Wk, Wv, base);

    dim3 agrid(SS / 64, BB * HH);  // 32 x 32
    attn_kernel<<<agrid, 256, ATT_SMEM_BYTES>>>(qp, kp, vp, out);
}

// round 4
// speedup vs baseline: 1.5824x; 1.5824x over previous
#include <cuda_runtime.h>
#include <cuda_bf16.h>
#include <mma.h>
#include <cstdint>

using namespace nvcuda;

// Problem dims
#define BB   2
#define SS   2048
#define DIM  2048
#define HH   16
#define HD   128

#define QKV_ELEMS (BB * HH * SS * HD)
__device__ float g_scratch[3 * QKV_ELEMS];

__device__ __forceinline__ float f2tf32(float x) {
    uint32_t u;
    asm("cvt.rna.tf32.f32 %0, %1;" : "=r"(u) : "f"(x));
    return __uint_as_float(u);
}
__device__ __forceinline__ uint32_t f2tf32u(float x) {
    uint32_t u;
    asm("cvt.rna.tf32.f32 %0, %1;" : "=r"(u) : "f"(x));
    return u;
}
__device__ __forceinline__ float ex2(float x) {
    float r;
    asm("ex2.approx.f32 %0, %1;" : "=f"(r) : "f"(x));
    return r;
}
__device__ __forceinline__ void mma_tf32(float* d, const uint32_t* a, uint32_t b0, uint32_t b1) {
    asm volatile(
        "mma.sync.aligned.m16n8k8.row.col.f32.tf32.tf32.f32 "
        "{%0,%1,%2,%3}, {%4,%5,%6,%7}, {%8,%9}, {%0,%1,%2,%3};\n"
        : "+f"(d[0]), "+f"(d[1]), "+f"(d[2]), "+f"(d[3])
        : "r"(a[0]), "r"(a[1]), "r"(a[2]), "r"(a[3]), "r"(b0), "r"(b1));
}

// ---------------------------------------------------------------------------
// Fused projection GEMM (unchanged from passing round): grid (16,32,3)
// ---------------------------------------------------------------------------
#define GEMM_SMEM_FLOATS (2 * (128 * 36) + 2 * (32 * 132))
#define GEMM_SMEM_BYTES  (GEMM_SMEM_FLOATS * 4)

__global__ void __launch_bounds__(256, 1)
proj_gemm_fused(const float* __restrict__ A,
                const float* __restrict__ Wq,
                const float* __restrict__ Wk,
                const float* __restrict__ Wv,
                float* __restrict__ scratch) {
    extern __shared__ float sm[];
    float* As[2] = { sm, sm + 128 * 36 };
    float* Bs[2] = { sm + 2 * 128 * 36, sm + 2 * 128 * 36 + 32 * 132 };

    const int tid  = threadIdx.x;
    const int warp = tid >> 5;
    const int wm   = warp >> 2;
    const int wn   = warp & 3;
    const int bm   = blockIdx.y;
    const int bn   = blockIdx.x;
    const int z    = blockIdx.z;

    const float* Wm = (z == 0) ? Wq : (z == 1) ? Wk : Wv;
    float* outp = scratch + (size_t)z * QKV_ELEMS;

    const float* Ag = A + (size_t)bm * 128 * DIM;
    const float* Bg = Wm + bn * 128;

    wmma::fragment<wmma::accumulator, 16, 16, 8, float> acc[4][2];
#pragma unroll
    for (int i = 0; i < 4; ++i)
#pragma unroll
        for (int j = 0; j < 2; ++j) wmma::fill_fragment(acc[i][j], 0.0f);

    const int ar = tid >> 3;
    const int ac = (tid & 7) * 4;
    const int bk = tid >> 5;
    const int bc = (tid & 31) * 4;

    float4 ra[4], rb[4];

#pragma unroll
    for (int p = 0; p < 4; ++p)
        ra[p] = *(const float4*)(Ag + (size_t)(p * 32 + ar) * DIM + ac);
#pragma unroll
    for (int p = 0; p < 4; ++p)
        rb[p] = *(const float4*)(Bg + (size_t)(p * 8 + bk) * DIM + bc);
#pragma unroll
    for (int p = 0; p < 4; ++p) {
        float* d = As[0] + (p * 32 + ar) * 36 + ac;
        d[0] = f2tf32(ra[p].x); d[1] = f2tf32(ra[p].y);
        d[2] = f2tf32(ra[p].z); d[3] = f2tf32(ra[p].w);
    }
#pragma unroll
    for (int p = 0; p < 4; ++p) {
        float* d = Bs[0] + (p * 8 + bk) * 132 + bc;
        d[0] = f2tf32(rb[p].x); d[1] = f2tf32(rb[p].y);
        d[2] = f2tf32(rb[p].z); d[3] = f2tf32(rb[p].w);
    }
    __syncthreads();

    const int NKT = DIM / 32;
#pragma unroll 1
    for (int kt = 0; kt < NKT; ++kt) {
        const int buf = kt & 1;
        if (kt < NKT - 1) {
            const int ko = (kt + 1) * 32;
#pragma unroll
            for (int p = 0; p < 4; ++p)
                ra[p] = *(const float4*)(Ag + (size_t)(p * 32 + ar) * DIM + ko + ac);
#pragma unroll
            for (int p = 0; p < 4; ++p)
                rb[p] = *(const float4*)(Bg + (size_t)(ko + p * 8 + bk) * DIM + bc);
        }
#pragma unroll
        for (int ks = 0; ks < 4; ++ks) {
            wmma::fragment<wmma::matrix_a, 16, 16, 8, wmma::precision::tf32, wmma::row_major> fa[4];
            wmma::fragment<wmma::matrix_b, 16, 16, 8, wmma::precision::tf32, wmma::row_major> fb[2];
#pragma unroll
            for (int i = 0; i < 4; ++i)
                wmma::load_matrix_sync(fa[i], As[buf] + (wm * 64 + i * 16) * 36 + ks * 8, 36);
#pragma unroll
            for (int j = 0; j < 2; ++j)
                wmma::load_matrix_sync(fb[j], Bs[buf] + (ks * 8) * 132 + wn * 32 + j * 16, 132);
#pragma unroll
            for (int i = 0; i < 4; ++i)
#pragma unroll
                for (int j = 0; j < 2; ++j)
                    wmma::mma_sync(acc[i][j], fa[i], fb[j], acc[i][j]);
        }
        if (kt < NKT - 1) {
            const int nb = buf ^ 1;
#pragma unroll
            for (int p = 0; p < 4; ++p) {
                float* d = As[nb] + (p * 32 + ar) * 36 + ac;
                d[0] = f2tf32(ra[p].x); d[1] = f2tf32(ra[p].y);
                d[2] = f2tf32(ra[p].z); d[3] = f2tf32(ra[p].w);
            }
#pragma unroll
            for (int p = 0; p < 4; ++p) {
                float* d = Bs[nb] + (p * 8 + bk) * 132 + bc;
                d[0] = f2tf32(rb[p].x); d[1] = f2tf32(rb[p].y);
                d[2] = f2tf32(rb[p].z); d[3] = f2tf32(rb[p].w);
            }
        }
        __syncthreads();
    }

    const int b  = bm >> 4;
    const int s0 = (bm & 15) * 128;
    float* Cg = outp + (((size_t)(b * HH + bn)) * SS + s0) * HD;
#pragma unroll
    for (int i = 0; i < 4; ++i)
#pragma unroll
        for (int j = 0; j < 2; ++j)
            wmma::store_matrix_sync(Cg + (wm * 64 + i * 16) * HD + wn * 32 + j * 16,
                                    acc[i][j], HD, wmma::mem_row_major);
}

// ---------------------------------------------------------------------------
// FA2-style flash attention with explicit mma.sync m16n8k8 tf32.
// CTA = 128 Q rows (8 warps x 16 rows), KV tile = 64 rows.
// Q frags + O accumulator + softmax state entirely in registers.
// smem: Ks[64][132] (S-phase B operand, conflict-free),
//       Vs[64][136] (PV-phase B operand, conflict-free).
// ---------------------------------------------------------------------------
#define KS_STRIDE 132
#define VS_STRIDE 136
#define ATT_SMEM_FLOATS (64 * KS_STRIDE + 64 * VS_STRIDE)
#define ATT_SMEM_BYTES  (ATT_SMEM_FLOATS * 4)

__global__ void __launch_bounds__(256, 1)
attn_kernel(const float* __restrict__ Q, const float* __restrict__ K,
            const float* __restrict__ V, float* __restrict__ outp) {
    extern __shared__ float sm[];
    float* Ks = sm;                    // 64 x 132
    float* Vs = sm + 64 * KS_STRIDE;   // 64 x 136

    const int qb   = (gridDim.x - 1) - blockIdx.x;  // heavy blocks first
    const int bh   = blockIdx.y;
    const int tid  = threadIdx.x;
    const int warp = tid >> 5;
    const int lane = tid & 31;
    const int gid  = lane >> 2;   // group id 0..7 (row within half-tile)
    const int tig  = lane & 3;    // thread in group

    // fold 1/sqrt(128) and log2(e) into Q so we can use ex2 directly
    const float qscale = 0.08838834764831845f * 1.4426950408889634f;

    // ---- load Q fragments (held in registers for whole kernel) ----
    const float* Qg = Q + ((size_t)bh * SS + qb * 128 + warp * 16) * HD;
    uint32_t qa[16][4];
#pragma unroll
    for (int kk = 0; kk < 16; ++kk) {
        const int c = kk * 8 + tig;
        qa[kk][0] = f2tf32u(Qg[(size_t)gid * HD + c] * qscale);
        qa[kk][1] = f2tf32u(Qg[(size_t)(gid + 8) * HD + c] * qscale);
        qa[kk][2] = f2tf32u(Qg[(size_t)gid * HD + c + 4] * qscale);
        qa[kk][3] = f2tf32u(Qg[(size_t)(gid + 8) * HD + c + 4] * qscale);
    }

    float o[16][4];
#pragma unroll
    for (int j = 0; j < 16; ++j) { o[j][0] = o[j][1] = o[j][2] = o[j][3] = 0.0f; }
    float m0 = -1e30f, m1 = -1e30f, l0 = 0.0f, l1 = 0.0f;

    const int row0 = qb * 128 + warp * 16;     // warp's min row
    const int nkv  = 2 * qb + 2;               // KV blocks of 64

    const float* Kbh = K + (size_t)bh * SS * HD;
    const float* Vbh = V + (size_t)bh * SS * HD;

#pragma unroll 1
    for (int kb = 0; kb < nkv; ++kb) {
        // ---- fill K/V tiles (fp32 -> tf32 at store) ----
        const float4* K4 = (const float4*)(Kbh + (size_t)kb * 64 * HD);
        const float4* V4 = (const float4*)(Vbh + (size_t)kb * 64 * HD);
#pragma unroll
        for (int p = 0; p < 8; ++p) {
            const int i  = tid + p * 256;   // 0..2047
            const int r  = i >> 5;
            const int c4 = i & 31;
            float4 kq = K4[r * 32 + c4];
            float4 vq = V4[r * 32 + c4];
            float4 ko, vo;
            ko.x = f2tf32(kq.x); ko.y = f2tf32(kq.y); ko.z = f2tf32(kq.z); ko.w = f2tf32(kq.w);
            vo.x = f2tf32(vq.x); vo.y = f2tf32(vq.y); vo.z = f2tf32(vq.z); vo.w = f2tf32(vq.w);
            *(float4*)(Ks + r * KS_STRIDE + c4 * 4) = ko;
            *(float4*)(Vs + r * VS_STRIDE + c4 * 4) = vo;
        }
        __syncthreads();

        const int col0 = kb * 64;
        const bool full_skip = col0 > (row0 + 15);   // whole warp tile masked
        if (!full_skip) {
            // ---- S = Q K^T : 16x64 per warp ----
            float sacc[8][4];
#pragma unroll
            for (int j = 0; j < 8; ++j) { sacc[j][0] = sacc[j][1] = sacc[j][2] = sacc[j][3] = 0.0f; }
#pragma unroll
            for (int kk = 0; kk < 16; ++kk) {
                const int kc = kk * 8 + tig;
#pragma unroll
                for (int j = 0; j < 8; ++j) {
                    const float* kp = Ks + (8 * j + gid) * KS_STRIDE + kc;
                    mma_tf32(sacc[j], qa[kk], __float_as_uint(kp[0]), __float_as_uint(kp[4]));
                }
            }

            // ---- mask + online softmax (log2 domain) ----
            const int rg0 = row0 + gid;
            const int rg1 = rg0 + 8;
            const bool need_mask = (col0 + 63) > row0;
            if (need_mask) {
#pragma unroll
                for (int j = 0; j < 8; ++j) {
                    const int c = col0 + 8 * j + 2 * tig;
                    if (c > rg0)     sacc[j][0] = -1e30f;
                    if (c + 1 > rg0) sacc[j][1] = -1e30f;
                    if (c > rg1)     sacc[j][2] = -1e30f;
                    if (c + 1 > rg1) sacc[j][3] = -1e30f;
                }
            }
            float a0 = -1e30f, a1 = -1e30f;
#pragma unroll
            for (int j = 0; j < 8; ++j) {
                a0 = fmaxf(a0, fmaxf(sacc[j][0], sacc[j][1]));
                a1 = fmaxf(a1, fmaxf(sacc[j][2], sacc[j][3]));
            }
            a0 = fmaxf(a0, __shfl_xor_sync(0xffffffffu, a0, 1));
            a0 = fmaxf(a0, __shfl_xor_sync(0xffffffffu, a0, 2));
            a1 = fmaxf(a1, __shfl_xor_sync(0xffffffffu, a1, 1));
            a1 = fmaxf(a1, __shfl_xor_sync(0xffffffffu, a1, 2));

            const float mn0 = fmaxf(m0, a0);
            const float mn1 = fmaxf(m1, a1);
            const float al0 = ex2(m0 - mn0);
            const float al1 = ex2(m1 - mn1);
            m0 = mn0; m1 = mn1;

            float s0 = 0.0f, s1 = 0.0f;
#pragma unroll
            for (int j = 0; j < 8; ++j) {
                sacc[j][0] = ex2(sacc[j][0] - mn0);
                sacc[j][1] = ex2(sacc[j][1] - mn0);
                sacc[j][2] = ex2(sacc[j][2] - mn1);
                sacc[j][3] = ex2(sacc[j][3] - mn1);
                s0 += sacc[j][0] + sacc[j][1];
                s1 += sacc[j][2] + sacc[j][3];
            }
            s0 += __shfl_xor_sync(0xffffffffu, s0, 1);
            s0 += __shfl_xor_sync(0xffffffffu, s0, 2);
            s1 += __shfl_xor_sync(0xffffffffu, s1, 1);
            s1 += __shfl_xor_sync(0xffffffffu, s1, 2);
            l0 = l0 * al0 + s0;
            l1 = l1 * al1 + s1;

            // rescale O
#pragma unroll
            for (int j = 0; j < 16; ++j) {
                o[j][0] *= al0; o[j][1] *= al0;
                o[j][2] *= al1; o[j][3] *= al1;
            }

            // ---- O += P V : P (16x64) C-layout -> A-layout via shfl ----
            const int base = lane & ~3;
            const int srcA = base + (tig >> 1);
            const int srcB = srcA + 2;
            const bool odd = (tig & 1);
#pragma unroll
            for (int kk = 0; kk < 8; ++kk) {
                float pA0 = __shfl_sync(0xffffffffu, sacc[kk][0], srcA);
                float pA1 = __shfl_sync(0xffffffffu, sacc[kk][1], srcA);
                float pB0 = __shfl_sync(0xffffffffu, sacc[kk][0], srcB);
                float pB1 = __shfl_sync(0xffffffffu, sacc[kk][1], srcB);
                float pC0 = __shfl_sync(0xffffffffu, sacc[kk][2], srcA);
                float pC1 = __shfl_sync(0xffffffffu, sacc[kk][3], srcA);
                float pD0 = __shfl_sync(0xffffffffu, sacc[kk][2], srcB);
                float pD1 = __shfl_sync(0xffffffffu, sacc[kk][3], srcB);
                uint32_t pa[4];
                pa[0] = f2tf32u(odd ? pA1 : pA0);   // (gid,   k=8kk+tig)
                pa[1] = f2tf32u(odd ? pC1 : pC0);   // (gid+8, k=8kk+tig)
                pa[2] = f2tf32u(odd ? pB1 : pB0);   // (gid,   k=8kk+tig+4)
                pa[3] = f2tf32u(odd ? pD1 : pD0);   // (gid+8, k=8kk+tig+4)

                const float* v0 = Vs + (kk * 8 + tig) * VS_STRIDE + gid;
                const float* v1 = Vs + (kk * 8 + tig + 4) * VS_STRIDE + gid;
#pragma unroll
                for (int jn = 0; jn < 16; ++jn) {
                    mma_tf32(o[jn], pa,
                             __float_as_uint(v0[8 * jn]),
                             __float_as_uint(v1[8 * jn]));
                }
            }
        }
        __syncthreads();
    }

    // ---- epilogue: O / l -> gmem ----
    const float inv0 = 1.0f / l0;
    const float inv1 = 1.0f / l1;
    float* Og = outp + ((size_t)bh * SS + qb * 128 + warp * 16) * HD;
#pragma unroll
    for (int jn = 0; jn < 16; ++jn) {
        const int c = 8 * jn + 2 * tig;
        float2 r0 = make_float2(o[jn][0] * inv0, o[jn][1] * inv0);
        float2 r1 = make_float2(o[jn][2] * inv1, o[jn][3] * inv1);
        *(float2*)(Og + (size_t)gid * HD + c)       = r0;
        *(float2*)(Og + (size_t)(gid + 8) * HD + c) = r1;
    }
}

// ---------------------------------------------------------------------------
// kernel_launch
// ---------------------------------------------------------------------------
extern "C" void kernel_launch(void* const* d_in, const int* in_sizes, int n_in,
                              void* d_out, int out_size) {
    const float* hs = (const float*)d_in[0];
    const float* Wq = (const float*)d_in[2];
    const float* Wk = (const float*)d_in[3];
    const float* Wv = (const float*)d_in[4];
    float* out = (float*)d_out;

    float* base = nullptr;
    cudaGetSymbolAddress((void**)&base, g_scratch);
    float* qp = base;
    float* kp = base + QKV_ELEMS;
    float* vp = base + 2 * QKV_ELEMS;

    cudaFuncSetAttribute(proj_gemm_fused, cudaFuncAttributeMaxDynamicSharedMemorySize, GEMM_SMEM_BYTES);
    cudaFuncSetAttribute(attn_kernel, cudaFuncAttributeMaxDynamicSharedMemorySize, ATT_SMEM_BYTES);

    dim3 ggrid(DIM / 128, (BB * SS) / 128, 3);  // 16 x 32 x 3
    proj_gemm_fused<<<ggrid, 256, GEMM_SMEM_BYTES>>>(hs, Wq, Wk, Wv, base);

    dim3 agrid(SS / 128, BB * HH);  // 16 x 32
    attn_kernel<<<agrid, 256, ATT_SMEM_BYTES>>>(qp, kp, vp, out);
}